// round 5
// baseline (speedup 1.0000x reference)
#include <cuda_runtime.h>
#include <cuda_bf16.h>

#define BEV_H 512
#define BEV_W 512
#define BEV_C 64
#define HW (BEV_H * BEV_W)      // 262144
#define TILE 64                 // cells per pipeline stage
#define TPB  (HW / TILE)        // 4096 tiles per batch
#define GT   256                // gather threads per CTA

// Scratch: last-writer pillar index per BEV cell (up to 8 batches).
__device__ int g_last[8 * HW];
// Zero row for empty cells (zero-initialized, never written).
__device__ __align__(16) float g_zero[BEV_C];

// ---------------------------------------------------------------------------
// Scatter: last-occurrence-wins via atomicMax on pillar index.
// ---------------------------------------------------------------------------
__global__ void bev_scatter_kernel(const int* __restrict__ coords, int P) {
    int t = blockIdx.x * blockDim.x + threadIdx.x;
    int p0 = t * 4;
    if (p0 + 3 < P) {
        const int4* c4 = reinterpret_cast<const int4*>(coords + p0 * 3);
        int4 a  = __ldg(c4 + 0);  // b0 r0 c0 b1
        int4 bb = __ldg(c4 + 1);  // r1 c1 b2 r2
        int4 cc = __ldg(c4 + 2);  // c2 b3 r3 c3
        int bs[4] = {a.x, a.w, bb.z, cc.y};
        int rs[4] = {a.y, bb.x, bb.w, cc.z};
        int cs[4] = {a.z, bb.y, cc.x, cc.w};
#pragma unroll
        for (int k = 0; k < 4; k++) {
            int r = min(max(rs[k], 0), BEV_H - 1);
            int c = min(max(cs[k], 0), BEV_W - 1);
            atomicMax(&g_last[bs[k] * HW + r * BEV_W + c], p0 + k);
        }
    } else if (p0 < P) {
        for (int p = p0; p < P; p++) {
            int b = coords[3 * p + 0];
            int r = min(max(coords[3 * p + 1], 0), BEV_H - 1);
            int c = min(max(coords[3 * p + 2], 0), BEV_W - 1);
            atomicMax(&g_last[b * HW + r * BEV_W + c], p);
        }
    }
}

// ---------------------------------------------------------------------------
// Pipelined gather + transpose.
// Each CTA (256 thr) grid-strides over tiles of 64 cells, double-buffered
// 2x16KB smem. Steady state: STS tile i -> bar -> issue LDGs for tile i+1
// (+ g_last two ahead) -> STG tile i. Stores issue continuously.
//
// Phase 1 (per tile): 4-lane team per cell; lane q loads float4 q,q+4,q+8,q+12
//   of its row; STS with swizzle word(ch,cell)=ch*64 + (cell ^ (q(ch)<<3)).
// Phase 2: 4 iters; idx=it*256+tid; ch=idx>>4; quad=idx&15;
//   LDS.128 at ch*64 + (quad^(qq<<1))*4  (conflict-free), STG.128 along W.
// ---------------------------------------------------------------------------
__global__ void __launch_bounds__(GT) bev_gather_kernel(
    const float* __restrict__ feats,
    float* __restrict__ out,
    int ntiles) {
    __shared__ float smem[2][BEV_C * TILE];  // 2 x 16KB

    const int tid = threadIdx.x;
    const int q   = tid & 3;     // lane quarter within the 4-lane row team
    const int cw  = tid >> 2;    // 0..63: cell within tile
    const int csw = cw ^ (q << 3);
    const int stride = gridDim.x;

    int tile = blockIdx.x;
    if (tile >= ntiles) return;

    // ---- prologue: rows for tile, g_last for tile+stride ----
    int last = __ldg(&g_last[tile * TILE + cw]);
    const float4* row = reinterpret_cast<const float4*>(
        last >= 0 ? feats + (size_t)last * BEV_C : g_zero);
    float4 v0 = __ldg(row + q + 0);
    float4 v1 = __ldg(row + q + 4);
    float4 v2 = __ldg(row + q + 8);
    float4 v3 = __ldg(row + q + 12);

    int next_tile = tile + stride;
    int last1 = (next_tile < ntiles) ? __ldg(&g_last[next_tile * TILE + cw]) : -1;

    int p = 0;
    while (true) {
        // ---- STS current tile into buf p ----
        float* s = smem[p];
        float* s0 = s + (4 * (q + 0))  * TILE + csw;
        float* s1 = s + (4 * (q + 4))  * TILE + csw;
        float* s2 = s + (4 * (q + 8))  * TILE + csw;
        float* s3 = s + (4 * (q + 12)) * TILE + csw;
        s0[0 * TILE] = v0.x; s0[1 * TILE] = v0.y; s0[2 * TILE] = v0.z; s0[3 * TILE] = v0.w;
        s1[0 * TILE] = v1.x; s1[1 * TILE] = v1.y; s1[2 * TILE] = v1.z; s1[3 * TILE] = v1.w;
        s2[0 * TILE] = v2.x; s2[1 * TILE] = v2.y; s2[2 * TILE] = v2.z; s2[3 * TILE] = v2.w;
        s3[0 * TILE] = v3.x; s3[1 * TILE] = v3.y; s3[2 * TILE] = v3.z; s3[3 * TILE] = v3.w;

        __syncthreads();

        // ---- issue next tile's loads (fly during the STGs below) ----
        const bool have_next = next_tile < ntiles;
        int last2 = -1;
        if (have_next) {
            const float4* nrow = reinterpret_cast<const float4*>(
                last1 >= 0 ? feats + (size_t)last1 * BEV_C : g_zero);
            v0 = __ldg(nrow + q + 0);
            v1 = __ldg(nrow + q + 4);
            v2 = __ldg(nrow + q + 8);
            v3 = __ldg(nrow + q + 12);
            int nnt = next_tile + stride;
            if (nnt < ntiles) last2 = __ldg(&g_last[nnt * TILE + cw]);
        }

        // ---- STG current tile (float4 along W) ----
        const int b = tile >> 12;                 // tile / TPB (TPB=4096)
        const int pos_base = (tile & (TPB - 1)) * TILE;
        float* out_b = out + (size_t)b * BEV_C * HW + pos_base;
#pragma unroll
        for (int it = 0; it < (BEV_C * TILE / 4) / GT; it++) {   // 4 iters
            const int idx  = it * GT + tid;       // quad index 0..1023
            const int ch   = idx >> 4;            // 0..63
            const int quad = idx & 15;
            const int qq   = (ch >> 2) & 3;
            const int qs   = quad ^ (qq << 1);
            float4 vv = *reinterpret_cast<const float4*>(s + ch * TILE + qs * 4);
            *reinterpret_cast<float4*>(out_b + (size_t)ch * HW + quad * 4) = vv;
        }

        if (!have_next) break;
        tile = next_tile;
        next_tile = tile + stride;
        last1 = last2;
        p ^= 1;
    }
}

extern "C" void kernel_launch(void* const* d_in, const int* in_sizes, int n_in,
                              void* d_out, int out_size) {
    const float* feats  = (const float*)d_in[0];   // (P, 64) float32
    const int*   coords = (const int*)d_in[1];     // (P, 3) int32
    float*       out    = (float*)d_out;           // (B, 64, 512, 512) float32

    int P = in_sizes[0] / BEV_C;
    int B = out_size / (BEV_C * HW);
    if (B > 8) B = 8;
    int ncells = B * HW;
    int ntiles = ncells / TILE;

    // 1) init last-index grid to -1 (memset node; 0xFF bytes == -1 int)
    void* lastPtr = nullptr;
    cudaGetSymbolAddress(&lastPtr, g_last);
    cudaMemsetAsync(lastPtr, 0xFF, (size_t)ncells * sizeof(int), 0);

    // 2) scatter
    int nt = (P + 3) / 4;
    bev_scatter_kernel<<<(nt + 255) / 256, 256>>>(coords, P);

    // 3) pipelined gather + transpose (grid-stride; ~8 CTAs/SM nominal)
    int gblocks = 148 * 8;
    if (gblocks > ntiles) gblocks = ntiles;
    bev_gather_kernel<<<gblocks, GT>>>(feats, out, ntiles);
}

// round 6
// speedup vs baseline: 1.2281x; 1.2281x over previous
#include <cuda_runtime.h>
#include <cuda_bf16.h>

#define BEV_H 512
#define BEV_W 512
#define BEV_C 64
#define HW (BEV_H * BEV_W)   // 262144 = 2^18

// Scratch: last-writer pillar index per BEV cell (up to 8 batches).
__device__ int g_last[8 * HW];
// Zero row for empty cells (zero-initialized, never written).
__device__ __align__(16) float g_zero[BEV_C];

// ---------------------------------------------------------------------------
// Scatter: last-occurrence-wins via atomicMax on pillar index.
// ---------------------------------------------------------------------------
__global__ void bev_scatter_kernel(const int* __restrict__ coords, int P) {
    int t = blockIdx.x * blockDim.x + threadIdx.x;
    int p0 = t * 4;
    if (p0 + 3 < P) {
        const int4* c4 = reinterpret_cast<const int4*>(coords + p0 * 3);
        int4 a  = __ldg(c4 + 0);  // b0 r0 c0 b1
        int4 bb = __ldg(c4 + 1);  // r1 c1 b2 r2
        int4 cc = __ldg(c4 + 2);  // c2 b3 r3 c3
        int bs[4] = {a.x, a.w, bb.z, cc.y};
        int rs[4] = {a.y, bb.x, bb.w, cc.z};
        int cs[4] = {a.z, bb.y, cc.x, cc.w};
#pragma unroll
        for (int k = 0; k < 4; k++) {
            int r = min(max(rs[k], 0), BEV_H - 1);
            int c = min(max(cs[k], 0), BEV_W - 1);
            atomicMax(&g_last[bs[k] * HW + r * BEV_W + c], p0 + k);
        }
    } else if (p0 < P) {
        for (int p = p0; p < P; p++) {
            int b = coords[3 * p + 0];
            int r = min(max(coords[3 * p + 1], 0), BEV_H - 1);
            int c = min(max(coords[3 * p + 2], 0), BEV_W - 1);
            atomicMax(&g_last[b * HW + r * BEV_W + c], p);
        }
    }
}

// ---------------------------------------------------------------------------
// Gather + transpose, warp-autonomous, ZERO smem / ZERO barriers.
// Each warp owns 8 consecutive cells. Lane (q = l&3, cw = l>>2):
//   Load:  lane q of cell cw's 4-lane team loads float4 #q, q+4, q+8, q+12 of
//          that cell's row -> per LDG.128 the warp touches 8 rows x 64B
//          contiguous = 8 L1 wavefronts (vs 32 for thread-per-cell loads).
//   Store: lane holds channels {16k+4q+j}; 16 STG.32, each instruction writes
//          4 channels x 8 consecutive cells = 4 aligned 32B sectors (4 wf).
//          Consecutive warps = consecutive 8-cell groups, so neighboring 32B
//          chunks of the same channel merge into full 128B lines in L2.
// ---------------------------------------------------------------------------
__global__ void __launch_bounds__(256) bev_gather_kernel(
    const float* __restrict__ feats,
    float* __restrict__ out) {
    const int t  = blockIdx.x * 256 + threadIdx.x;
    const int w  = t >> 5;          // global warp id == 8-cell group id
    const int l  = t & 31;
    const int q  = l & 3;           // lane quarter within the 4-lane row team
    const int cw = l >> 2;          // 0..7: cell within group

    const int base = w * 8;                 // first cell of group (8 | HW)
    const int cell = base + cw;

    const int last = __ldg(&g_last[cell]);
    const float4* row = reinterpret_cast<const float4*>(
        last >= 0 ? feats + (size_t)last * BEV_C : g_zero);

    float4 v0 = __ldg(row + q + 0);   // channels 4q+0..3
    float4 v1 = __ldg(row + q + 4);   // channels 16+4q+0..3
    float4 v2 = __ldg(row + q + 8);   // channels 32+4q+0..3
    float4 v3 = __ldg(row + q + 12);  // channels 48+4q+0..3

    const int b   = base >> 18;       // group never crosses a batch
    const int pos = base & (HW - 1);
    float* ob = out + (size_t)b * (BEV_C * HW) + pos + cw;

    const size_t chb = (size_t)(4 * q) * HW;  // channel offset base for this lane
#pragma unroll
    for (int k = 0; k < 4; k++) {
        float4 v = (k == 0) ? v0 : (k == 1) ? v1 : (k == 2) ? v2 : v3;
        float* o = ob + (size_t)(16 * k) * HW + chb;
        o[0 * HW] = v.x;
        o[1 * HW] = v.y;
        o[2 * (size_t)HW] = v.z;
        o[3 * (size_t)HW] = v.w;
    }
}

extern "C" void kernel_launch(void* const* d_in, const int* in_sizes, int n_in,
                              void* d_out, int out_size) {
    const float* feats  = (const float*)d_in[0];   // (P, 64) float32
    const int*   coords = (const int*)d_in[1];     // (P, 3) int32
    float*       out    = (float*)d_out;           // (B, 64, 512, 512) float32

    int P = in_sizes[0] / BEV_C;
    int B = out_size / (BEV_C * HW);
    if (B > 8) B = 8;
    int ncells = B * HW;

    // 1) init last-index grid to -1 (memset node; 0xFF bytes == -1 int)
    void* lastPtr = nullptr;
    cudaGetSymbolAddress(&lastPtr, g_last);
    cudaMemsetAsync(lastPtr, 0xFF, (size_t)ncells * sizeof(int), 0);

    // 2) scatter
    int nt = (P + 3) / 4;
    bev_scatter_kernel<<<(nt + 255) / 256, 256>>>(coords, P);

    // 3) gather + transpose: one warp per 8 cells, 8 warps per CTA
    int gblocks = ncells / 64;   // (ncells/8 groups) / (8 warps per CTA)
    bev_gather_kernel<<<gblocks, 256>>>(feats, out);
}